// round 1
// baseline (speedup 1.0000x reference)
#include <cuda_runtime.h>
#include <math.h>
#include <stdint.h>

#define NB 16
#define NS 1024
#define ND 128
#define NH 4
#define NEGV -1e9f
#define LNEPS 1e-5f

// Scratch (device globals: allocation-free per harness rules)
__device__ float g_q[NB*NH*NS*ND];
__device__ float g_k[NB*NH*NS*ND];
__device__ float g_v[NB*NH*NS*ND];
__device__ float g_ctx[NB*NH*NS*ND];
__device__ float g_mean[NB];
__device__ float g_rstd[NB];
__device__ int   g_edge64;   // 1 if edge matrix is int64, 0 if int32

// ---------------------------------------------------------------------------
// K1: per-batch LayerNorm stats over (S,D); also sniff edge dtype
// ---------------------------------------------------------------------------
__global__ void ln_stats_kernel(const float* __restrict__ x,
                                const int* __restrict__ edge) {
    int b = blockIdx.x;
    const float4* xb = (const float4*)(x + (size_t)b * NS * ND);
    const int n4 = NS * ND / 4;   // 32768
    float s = 0.f, ss = 0.f;
    for (int i = threadIdx.x; i < n4; i += blockDim.x) {
        float4 v = xb[i];
        s  += v.x + v.y + v.z + v.w;
        ss += v.x*v.x + v.y*v.y + v.z*v.z + v.w*v.w;
    }
    __shared__ float sh[256], sh2[256];
    sh[threadIdx.x] = s; sh2[threadIdx.x] = ss;
    __syncthreads();
    for (int o = 128; o > 0; o >>= 1) {
        if (threadIdx.x < o) {
            sh[threadIdx.x]  += sh[threadIdx.x + o];
            sh2[threadIdx.x] += sh2[threadIdx.x + o];
        }
        __syncthreads();
    }
    if (threadIdx.x == 0) {
        float inv_n = 1.f / (float)(NS * ND);
        float mu  = sh[0] * inv_n;
        float var = sh2[0] * inv_n - mu * mu;
        g_mean[b] = mu;
        g_rstd[b] = rsqrtf(var + LNEPS);
        if (b == 0) {
            // int64 little-endian => every odd int32 word is 0 (values in [0,5))
            int any = 0;
            #pragma unroll
            for (int i = 0; i < 64; i++) any |= edge[2*i + 1];
            g_edge64 = (any == 0) ? 1 : 0;
        }
    }
}

// ---------------------------------------------------------------------------
// K2: fused normalize + QKV projection GEMM
// C[row, col] = sum_d (x[row,d]-mu)*rstd * W_in[col, d] + b_in[col]
// rows = B*S = 16384, cols = H*3D = 1536, K = 128
// 64x64 tile, 16x16 threads, 4x4 per-thread tile, k-major smem.
// ---------------------------------------------------------------------------
__global__ __launch_bounds__(256) void qkv_kernel(const float* __restrict__ x,
                                                  const float* __restrict__ W_in,
                                                  const float* __restrict__ b_in) {
    const int n0 = blockIdx.x * 64;     // col tile (24 tiles)
    const int m0 = blockIdx.y * 64;     // row tile (256 tiles)
    __shared__ float As[64][68];
    __shared__ float Bs[64][68];
    const int tid = threadIdx.x;
    const int tx = tid & 15, ty = tid >> 4;
    const int b = m0 >> 10;
    const float mean = g_mean[b], rstd = g_rstd[b];
    float acc[4][4];
    #pragma unroll
    for (int i = 0; i < 4; i++)
        #pragma unroll
        for (int j = 0; j < 4; j++) acc[i][j] = 0.f;

    for (int kk = 0; kk < ND; kk += 64) {
        const int c = (tid & 15) * 4;
        for (int r = tid >> 4; r < 64; r += 16) {
            float4 a = *(const float4*)&x[(size_t)(m0 + r) * ND + kk + c];
            As[c+0][r] = (a.x - mean) * rstd;
            As[c+1][r] = (a.y - mean) * rstd;
            As[c+2][r] = (a.z - mean) * rstd;
            As[c+3][r] = (a.w - mean) * rstd;
            float4 w = *(const float4*)&W_in[(size_t)(n0 + r) * ND + kk + c];
            Bs[c+0][r] = w.x; Bs[c+1][r] = w.y; Bs[c+2][r] = w.z; Bs[c+3][r] = w.w;
        }
        __syncthreads();
        #pragma unroll 8
        for (int k = 0; k < 64; k++) {
            float4 a4 = *(const float4*)&As[k][ty*4];
            float4 b4 = *(const float4*)&Bs[k][tx*4];
            float av[4] = {a4.x, a4.y, a4.z, a4.w};
            float bv[4] = {b4.x, b4.y, b4.z, b4.w};
            #pragma unroll
            for (int i = 0; i < 4; i++)
                #pragma unroll
                for (int j = 0; j < 4; j++) acc[i][j] += av[i] * bv[j];
        }
        __syncthreads();
    }

    // Epilogue: add bias, scatter into q/k/v [B,H,S,D]
    #pragma unroll
    for (int i = 0; i < 4; i++) {
        int row = m0 + ty*4 + i;
        int s = row & (NS - 1);
        #pragma unroll
        for (int j = 0; j < 4; j++) {
            int col = n0 + tx*4 + j;
            float v = acc[i][j] + b_in[col];
            int h = col / 384;
            int r = col - h * 384;
            int which = r >> 7;     // 0:q 1:k 2:v
            int d = r & 127;
            float* dst = (which == 0) ? g_q : (which == 1) ? g_k : g_v;
            dst[(((size_t)(b*NH + h)) * NS + s) * ND + d] = v;
        }
    }
}

// ---------------------------------------------------------------------------
// K3: fused flash-style attention.
// One block = (b, h, 64-query tile). 256 threads.
// smem: Qs[128][68] k-major, Ks[64][68] k-major (d chunked by 64),
//       Vs[64][128], Ps[64][68].  Total 102400 B dynamic.
// ---------------------------------------------------------------------------
#define QS_OFF 0
#define KS_OFF (128*68)
#define VS_OFF (128*68 + 64*68)
#define PS_OFF (128*68 + 64*68 + 64*128)
#define ATTN_SMEM_FLOATS (128*68 + 64*68 + 64*128 + 64*68)

__global__ __launch_bounds__(256, 2) void attn_kernel(const int* __restrict__ edge) {
    extern __shared__ float sm[];
    float* Qs = sm + QS_OFF;
    float* Ks = sm + KS_OFF;
    float* Vs = sm + VS_OFF;
    float* Ps = sm + PS_OFF;

    const int bh = blockIdx.x >> 4;
    const int qt = blockIdx.x & 15;
    const int h  = bh & 3;
    const int m0 = qt * 64;
    const int tid = threadIdx.x;
    const int tx = tid & 15, ty = tid >> 4;
    const int hid = h + 1;
    const float scale = 0.08838834764831845f;   // 1/sqrt(128)

    const float* Qg = g_q + (size_t)bh * NS * ND;
    const float* Kg = g_k + (size_t)bh * NS * ND;
    const float* Vg = g_v + (size_t)bh * NS * ND;
    const int is64 = g_edge64;

    // Load Q tile transposed: Qs[d][m]
    {
        const int c = (tid & 31) * 4;
        for (int r = tid >> 5; r < 64; r += 8) {
            float4 q4 = *(const float4*)&Qg[(size_t)(m0 + r) * ND + c];
            Qs[(c+0)*68 + r] = q4.x;
            Qs[(c+1)*68 + r] = q4.y;
            Qs[(c+2)*68 + r] = q4.z;
            Qs[(c+3)*68 + r] = q4.w;
        }
    }

    float rowmax[4], rowsum[4], o[4][8];
    #pragma unroll
    for (int i = 0; i < 4; i++) {
        rowmax[i] = -1e30f; rowsum[i] = 0.f;
        #pragma unroll
        for (int j = 0; j < 8; j++) o[i][j] = 0.f;
    }

    for (int n0 = 0; n0 < NS; n0 += 64) {
        __syncthreads();   // prior GEMM2 done reading Vs/Ps; Q load done (1st iter)

        // Load K chunk0 (d 0..63) transposed + full V tile
        {
            const int c16 = (tid & 15) * 4;
            for (int r = tid >> 4; r < 64; r += 16) {
                float4 k4 = *(const float4*)&Kg[(size_t)(n0 + r) * ND + c16];
                Ks[(c16+0)*68 + r] = k4.x;
                Ks[(c16+1)*68 + r] = k4.y;
                Ks[(c16+2)*68 + r] = k4.z;
                Ks[(c16+3)*68 + r] = k4.w;
            }
            const int c32 = (tid & 31) * 4;
            for (int r = tid >> 5; r < 64; r += 8) {
                *(float4*)&Vs[r * ND + c32] =
                    *(const float4*)&Vg[(size_t)(n0 + r) * ND + c32];
            }
        }
        __syncthreads();

        float sc[4][4];
        #pragma unroll
        for (int i = 0; i < 4; i++)
            #pragma unroll
            for (int j = 0; j < 4; j++) sc[i][j] = 0.f;

        // GEMM1 chunk 0: d = 0..63
        #pragma unroll 8
        for (int k = 0; k < 64; k++) {
            float4 a4 = *(const float4*)&Qs[k*68 + ty*4];
            float4 b4 = *(const float4*)&Ks[k*68 + tx*4];
            float av[4] = {a4.x, a4.y, a4.z, a4.w};
            float bv[4] = {b4.x, b4.y, b4.z, b4.w};
            #pragma unroll
            for (int i = 0; i < 4; i++)
                #pragma unroll
                for (int j = 0; j < 4; j++) sc[i][j] += av[i] * bv[j];
        }
        __syncthreads();   // done reading Ks chunk0

        // Load K chunk1 (d 64..127)
        {
            const int c16 = (tid & 15) * 4;
            for (int r = tid >> 4; r < 64; r += 16) {
                float4 k4 = *(const float4*)&Kg[(size_t)(n0 + r) * ND + 64 + c16];
                Ks[(c16+0)*68 + r] = k4.x;
                Ks[(c16+1)*68 + r] = k4.y;
                Ks[(c16+2)*68 + r] = k4.z;
                Ks[(c16+3)*68 + r] = k4.w;
            }
        }
        __syncthreads();

        // GEMM1 chunk 1: d = 64..127
        #pragma unroll 8
        for (int k = 0; k < 64; k++) {
            float4 a4 = *(const float4*)&Qs[(64+k)*68 + ty*4];
            float4 b4 = *(const float4*)&Ks[k*68 + tx*4];
            float av[4] = {a4.x, a4.y, a4.z, a4.w};
            float bv[4] = {b4.x, b4.y, b4.z, b4.w};
            #pragma unroll
            for (int i = 0; i < 4; i++)
                #pragma unroll
                for (int j = 0; j < 4; j++) sc[i][j] += av[i] * bv[j];
        }

        // Scale + edge-type mask
        float tmax[4];
        #pragma unroll
        for (int i = 0; i < 4; i++) {
            const size_t mg = (size_t)(m0 + ty*4 + i) * NS;
            tmax[i] = -1e30f;
            #pragma unroll
            for (int j = 0; j < 4; j++) {
                size_t idx = mg + (n0 + tx*4 + j);
                int e = is64 ? edge[2*idx] : edge[idx];
                float s = sc[i][j] * scale + ((e == hid) ? 0.f : NEGV);
                sc[i][j] = s;
                tmax[i] = fmaxf(tmax[i], s);
            }
        }
        // Reduce over the 16 tx lanes (same ty-group within warp)
        #pragma unroll
        for (int i = 0; i < 4; i++)
            #pragma unroll
            for (int off = 8; off > 0; off >>= 1)
                tmax[i] = fmaxf(tmax[i], __shfl_xor_sync(0xffffffffu, tmax[i], off));

        float nm[4], f[4], tsum[4];
        #pragma unroll
        for (int i = 0; i < 4; i++) {
            nm[i] = fmaxf(rowmax[i], tmax[i]);
            f[i]  = __expf(rowmax[i] - nm[i]);
            rowmax[i] = nm[i];
            tsum[i] = 0.f;
            #pragma unroll
            for (int j = 0; j < 4; j++) {
                float p = __expf(sc[i][j] - nm[i]);
                sc[i][j] = p;
                tsum[i] += p;
            }
        }
        #pragma unroll
        for (int i = 0; i < 4; i++)
            #pragma unroll
            for (int off = 8; off > 0; off >>= 1)
                tsum[i] += __shfl_xor_sync(0xffffffffu, tsum[i], off);
        #pragma unroll
        for (int i = 0; i < 4; i++) {
            rowsum[i] = rowsum[i] * f[i] + tsum[i];
            #pragma unroll
            for (int j = 0; j < 8; j++) o[i][j] *= f[i];
            float4 p4 = make_float4(sc[i][0], sc[i][1], sc[i][2], sc[i][3]);
            *(float4*)&Ps[(ty*4 + i)*68 + tx*4] = p4;
        }
        __syncthreads();   // Ps fully written

        // GEMM2: O += P @ V
        #pragma unroll 8
        for (int n = 0; n < 64; n++) {
            float4 v0 = *(const float4*)&Vs[n*ND + tx*8];
            float4 v1 = *(const float4*)&Vs[n*ND + tx*8 + 4];
            #pragma unroll
            for (int i = 0; i < 4; i++) {
                float p = Ps[(ty*4 + i)*68 + n];
                o[i][0] += p*v0.x; o[i][1] += p*v0.y;
                o[i][2] += p*v0.z; o[i][3] += p*v0.w;
                o[i][4] += p*v1.x; o[i][5] += p*v1.y;
                o[i][6] += p*v1.z; o[i][7] += p*v1.w;
            }
        }
    }

    // Epilogue: divide by rowsum, write ctx[B,H,S,D]
    #pragma unroll
    for (int i = 0; i < 4; i++) {
        float inv = 1.f / rowsum[i];
        size_t base = ((size_t)bh * NS + (m0 + ty*4 + i)) * ND + tx*8;
        float4 o0 = make_float4(o[i][0]*inv, o[i][1]*inv, o[i][2]*inv, o[i][3]*inv);
        float4 o1 = make_float4(o[i][4]*inv, o[i][5]*inv, o[i][6]*inv, o[i][7]*inv);
        *(float4*)&g_ctx[base]     = o0;
        *(float4*)&g_ctx[base + 4] = o1;
    }
}

// ---------------------------------------------------------------------------
// K4: out projection.
// out[b,s,h*128+e] = sum_d ctx[b,h,s,d] * W_out[h,e,d] + b_out[h,e]
// rows = B*S, cols = H*D = 512. W_out flat is [512,128] with row = col.
// ---------------------------------------------------------------------------
__global__ __launch_bounds__(256) void outproj_kernel(const float* __restrict__ W_out,
                                                      const float* __restrict__ b_out,
                                                      float* __restrict__ out) {
    const int n0 = blockIdx.x * 64;   // 8 col tiles
    const int m0 = blockIdx.y * 64;   // 256 row tiles
    const int h = n0 >> 7;            // 64 | 128 => whole tile same head
    __shared__ float As[64][68];
    __shared__ float Bs[64][68];
    const int tid = threadIdx.x;
    const int tx = tid & 15, ty = tid >> 4;
    const int b = m0 >> 10;
    const int s0 = m0 & (NS - 1);
    const float* Ag = g_ctx + ((size_t)(b*NH + h) * NS + s0) * ND;

    float acc[4][4];
    #pragma unroll
    for (int i = 0; i < 4; i++)
        #pragma unroll
        for (int j = 0; j < 4; j++) acc[i][j] = 0.f;

    for (int kk = 0; kk < ND; kk += 64) {
        const int c = (tid & 15) * 4;
        for (int r = tid >> 4; r < 64; r += 16) {
            float4 a = *(const float4*)&Ag[(size_t)r * ND + kk + c];
            As[c+0][r] = a.x; As[c+1][r] = a.y; As[c+2][r] = a.z; As[c+3][r] = a.w;
            float4 w = *(const float4*)&W_out[(size_t)(n0 + r) * ND + kk + c];
            Bs[c+0][r] = w.x; Bs[c+1][r] = w.y; Bs[c+2][r] = w.z; Bs[c+3][r] = w.w;
        }
        __syncthreads();
        #pragma unroll 8
        for (int k = 0; k < 64; k++) {
            float4 a4 = *(const float4*)&As[k][ty*4];
            float4 b4 = *(const float4*)&Bs[k][tx*4];
            float av[4] = {a4.x, a4.y, a4.z, a4.w};
            float bv[4] = {b4.x, b4.y, b4.z, b4.w};
            #pragma unroll
            for (int i = 0; i < 4; i++)
                #pragma unroll
                for (int j = 0; j < 4; j++) acc[i][j] += av[i] * bv[j];
        }
        __syncthreads();
    }

    #pragma unroll
    for (int i = 0; i < 4; i++) {
        int row = m0 + ty*4 + i;
        int colb = n0 + tx*4;
        float4 r4 = make_float4(acc[i][0] + b_out[colb+0],
                                acc[i][1] + b_out[colb+1],
                                acc[i][2] + b_out[colb+2],
                                acc[i][3] + b_out[colb+3]);
        *(float4*)&out[(size_t)row * (NH*ND) + colb] = r4;
    }
}

// ---------------------------------------------------------------------------
extern "C" void kernel_launch(void* const* d_in, const int* in_sizes, int n_in,
                              void* d_out, int out_size) {
    const float* x     = (const float*)d_in[0];
    const int*   edge  = (const int*)d_in[1];   // int32 or int64 (auto-detected)
    const float* W_in  = (const float*)d_in[2];
    const float* b_in  = (const float*)d_in[3];
    const float* W_out = (const float*)d_in[4];
    const float* b_out = (const float*)d_in[5];
    float* out = (float*)d_out;

    static const size_t attn_smem = ATTN_SMEM_FLOATS * sizeof(float); // 102400
    cudaFuncSetAttribute((const void*)attn_kernel,
                         cudaFuncAttributeMaxDynamicSharedMemorySize,
                         (int)attn_smem);

    ln_stats_kernel<<<NB, 256>>>(x, edge);
    qkv_kernel<<<dim3(24, 256), 256>>>(x, W_in, b_in);
    attn_kernel<<<NB * NH * (NS / 64), 256, attn_smem>>>(edge);
    outproj_kernel<<<dim3(8, 256), 256>>>(W_out, b_out, out);
}

// round 2
// speedup vs baseline: 2.3204x; 2.3204x over previous
#include <cuda_runtime.h>
#include <math.h>
#include <stdint.h>

#define NB 16
#define NS 1024
#define ND 128
#define NH 4
#define NEGV -1e9f
#define LNEPS 1e-5f

// Scratch (device globals: allocation-free per harness rules)
__device__ float g_q[NB*NH*NS*ND];
__device__ float g_k[NB*NH*NS*ND];
__device__ float g_v[NB*NH*NS*ND];
__device__ float g_ctx[NB*NH*NS*ND];
__device__ float g_mean[NB];
__device__ float g_rstd[NB];
__device__ int   g_edge64;   // 1 if edge matrix is int64, 0 if int32

// ---------------------------------------------------------------------------
// K1: per-batch LayerNorm stats over (S,D); also sniff edge dtype
// ---------------------------------------------------------------------------
__global__ void ln_stats_kernel(const float* __restrict__ x,
                                const int* __restrict__ edge) {
    int b = blockIdx.x;
    const float4* xb = (const float4*)(x + (size_t)b * NS * ND);
    const int n4 = NS * ND / 4;
    float s = 0.f, ss = 0.f;
    for (int i = threadIdx.x; i < n4; i += blockDim.x) {
        float4 v = xb[i];
        s  += v.x + v.y + v.z + v.w;
        ss += v.x*v.x + v.y*v.y + v.z*v.z + v.w*v.w;
    }
    __shared__ float sh[256], sh2[256];
    sh[threadIdx.x] = s; sh2[threadIdx.x] = ss;
    __syncthreads();
    for (int o = 128; o > 0; o >>= 1) {
        if (threadIdx.x < o) {
            sh[threadIdx.x]  += sh[threadIdx.x + o];
            sh2[threadIdx.x] += sh2[threadIdx.x + o];
        }
        __syncthreads();
    }
    if (threadIdx.x == 0) {
        float inv_n = 1.f / (float)(NS * ND);
        float mu  = sh[0] * inv_n;
        float var = sh2[0] * inv_n - mu * mu;
        g_mean[b] = mu;
        g_rstd[b] = rsqrtf(var + LNEPS);
        if (b == 0) {
            int any = 0;
            #pragma unroll
            for (int i = 0; i < 64; i++) any |= edge[2*i + 1];
            g_edge64 = (any == 0) ? 1 : 0;
        }
    }
}

// ---------------------------------------------------------------------------
// K2: fused normalize + QKV projection GEMM (unchanged from R1)
// ---------------------------------------------------------------------------
__global__ __launch_bounds__(256) void qkv_kernel(const float* __restrict__ x,
                                                  const float* __restrict__ W_in,
                                                  const float* __restrict__ b_in) {
    const int n0 = blockIdx.x * 64;
    const int m0 = blockIdx.y * 64;
    __shared__ float As[64][68];
    __shared__ float Bs[64][68];
    const int tid = threadIdx.x;
    const int tx = tid & 15, ty = tid >> 4;
    const int b = m0 >> 10;
    const float mean = g_mean[b], rstd = g_rstd[b];
    float acc[4][4];
    #pragma unroll
    for (int i = 0; i < 4; i++)
        #pragma unroll
        for (int j = 0; j < 4; j++) acc[i][j] = 0.f;

    for (int kk = 0; kk < ND; kk += 64) {
        const int c = (tid & 15) * 4;
        for (int r = tid >> 4; r < 64; r += 16) {
            float4 a = *(const float4*)&x[(size_t)(m0 + r) * ND + kk + c];
            As[c+0][r] = (a.x - mean) * rstd;
            As[c+1][r] = (a.y - mean) * rstd;
            As[c+2][r] = (a.z - mean) * rstd;
            As[c+3][r] = (a.w - mean) * rstd;
            float4 w = *(const float4*)&W_in[(size_t)(n0 + r) * ND + kk + c];
            Bs[c+0][r] = w.x; Bs[c+1][r] = w.y; Bs[c+2][r] = w.z; Bs[c+3][r] = w.w;
        }
        __syncthreads();
        #pragma unroll 8
        for (int k = 0; k < 64; k++) {
            float4 a4 = *(const float4*)&As[k][ty*4];
            float4 b4 = *(const float4*)&Bs[k][tx*4];
            float av[4] = {a4.x, a4.y, a4.z, a4.w};
            float bv[4] = {b4.x, b4.y, b4.z, b4.w};
            #pragma unroll
            for (int i = 0; i < 4; i++)
                #pragma unroll
                for (int j = 0; j < 4; j++) acc[i][j] += av[i] * bv[j];
        }
        __syncthreads();
    }

    #pragma unroll
    for (int i = 0; i < 4; i++) {
        int row = m0 + ty*4 + i;
        int s = row & (NS - 1);
        #pragma unroll
        for (int j = 0; j < 4; j++) {
            int col = n0 + tx*4 + j;
            float v = acc[i][j] + b_in[col];
            int h = col / 384;
            int r = col - h * 384;
            int which = r >> 7;
            int d = r & 127;
            float* dst = (which == 0) ? g_q : (which == 1) ? g_k : g_v;
            dst[(((size_t)(b*NH + h)) * NS + s) * ND + d] = v;
        }
    }
}

// ---------------------------------------------------------------------------
// K3: flash attention with tf32 mma.sync (m16n8k8), cp.async double-buffered
// Block: 128 q rows (8 warps x 16), 64-key tiles, d=128.
// ---------------------------------------------------------------------------
#define KPAD 132
#define VPAD 136
#define PPAD 68
#define OFF_K0 0
#define OFF_K1 (64*KPAD)
#define OFF_V0 (2*64*KPAD)
#define OFF_V1 (2*64*KPAD + 64*VPAD)
#define OFF_P  (2*64*KPAD + 2*64*VPAD)
#define OFF_QSTG OFF_V1
#define ATTN_SMEM_FLOATS (2*64*KPAD + 2*64*VPAD + 128*PPAD)   // 43008 floats

__device__ __forceinline__ uint32_t f2tf(float f) {
    uint32_t r;
    asm("cvt.rna.tf32.f32 %0, %1;" : "=r"(r) : "f"(f));
    return r;
}

__device__ __forceinline__ void mma8(float& d0, float& d1, float& d2, float& d3,
                                     uint32_t a0, uint32_t a1, uint32_t a2, uint32_t a3,
                                     uint32_t b0, uint32_t b1) {
    asm volatile("mma.sync.aligned.m16n8k8.row.col.f32.tf32.tf32.f32 "
                 "{%0,%1,%2,%3}, {%4,%5,%6,%7}, {%8,%9}, {%0,%1,%2,%3};"
                 : "+f"(d0), "+f"(d1), "+f"(d2), "+f"(d3)
                 : "r"(a0), "r"(a1), "r"(a2), "r"(a3), "r"(b0), "r"(b1));
}

__device__ __forceinline__ void cp16(float* dst_smem, const float* src_gmem) {
    uint32_t d = (uint32_t)__cvta_generic_to_shared(dst_smem);
    asm volatile("cp.async.cg.shared.global [%0], [%1], 16;" :: "r"(d), "l"(src_gmem));
}

__device__ __forceinline__ void load_kv_async(const float* __restrict__ Kg,
                                              const float* __restrict__ Vg,
                                              int n0, float* Ks, float* Vs, int tid) {
    #pragma unroll
    for (int i = 0; i < 8; i++) {
        int q = i * 256 + tid;
        int row = q >> 5, c4 = q & 31;
        cp16(&Ks[row*KPAD + c4*4], Kg + (size_t)(n0 + row) * ND + c4*4);
        cp16(&Vs[row*VPAD + c4*4], Vg + (size_t)(n0 + row) * ND + c4*4);
    }
}

__global__ __launch_bounds__(256, 1) void attn_kernel(const int* __restrict__ edge) {
    extern __shared__ float sm[];
    const int tid  = threadIdx.x;
    const int w    = tid >> 5;
    const int lane = tid & 31;
    const int r4   = lane >> 2;   // groupID: 0..7
    const int c4   = lane & 3;    // threadID-in-group: 0..3

    const int bh = blockIdx.x >> 3;
    const int qt = blockIdx.x & 7;
    const int h  = bh & 3;
    const int m0 = qt * 128;
    const int hid = h + 1;
    const float scale = 0.08838834764831845f;

    const float* Qg = g_q + (size_t)bh * NS * ND;
    const float* Kg = g_k + (size_t)bh * NS * ND;
    const float* Vg = g_v + (size_t)bh * NS * ND;
    const int is64 = g_edge64;

    // Kick off K/V tile 0
    load_kv_async(Kg, Vg, 0, sm + OFF_K0, sm + OFF_V0, tid);
    asm volatile("cp.async.commit_group;");

    // Stage Q tile (128 rows) into smem (overlaps V1/P region; free until iter 0)
    {
        float* Qstg = sm + OFF_QSTG;
        #pragma unroll
        for (int i = 0; i < 16; i++) {
            int q = i * 256 + tid;
            int row = q >> 5, cc = q & 31;
            *(float4*)&Qstg[row*KPAD + cc*4] =
                *(const float4*)&Qg[(size_t)(m0 + row) * ND + cc*4];
        }
    }
    __syncthreads();

    // Gather Q A-fragments into registers (tf32, rounded)
    uint32_t Qf[64];
    {
        const float* Qstg = sm + OFF_QSTG;
        const int rl = 16*w + r4;
        #pragma unroll
        for (int t = 0; t < 16; t++) {
            Qf[4*t+0] = f2tf(Qstg[(rl    )*KPAD + 8*t + c4    ]);
            Qf[4*t+1] = f2tf(Qstg[(rl + 8)*KPAD + 8*t + c4    ]);
            Qf[4*t+2] = f2tf(Qstg[(rl    )*KPAD + 8*t + c4 + 4]);
            Qf[4*t+3] = f2tf(Qstg[(rl + 8)*KPAD + 8*t + c4 + 4]);
        }
    }
    __syncthreads();   // Q staging region may now be overwritten (V1 at iter 0)

    float o[16][4];
    #pragma unroll
    for (int j = 0; j < 16; j++)
        #pragma unroll
        for (int k = 0; k < 4; k++) o[j][k] = 0.f;
    float rowmax_lo = -1e30f, rowmax_hi = -1e30f;
    float rowsum_lo = 0.f, rowsum_hi = 0.f;

    float* Psw = sm + OFF_P + w * 16 * PPAD;
    const int mlo = m0 + 16*w + r4;
    const int mhi = mlo + 8;

    for (int it = 0; it < 16; ++it) {
        const int buf = it & 1;
        if (it + 1 < 16) {
            load_kv_async(Kg, Vg, (it + 1) * 64,
                          sm + (buf ? OFF_K0 : OFF_K1),
                          sm + (buf ? OFF_V0 : OFF_V1), tid);
            asm volatile("cp.async.commit_group;");
            asm volatile("cp.async.wait_group 1;");
        } else {
            asm volatile("cp.async.wait_group 0;");
        }
        __syncthreads();

        const float* Ks = sm + (buf ? OFF_K1 : OFF_K0);
        const float* Vs = sm + (buf ? OFF_V1 : OFF_V0);
        const int n0 = it * 64;

        // ---- QK^T: scores [16 x 64] per warp ----
        float acc[8][4];
        #pragma unroll
        for (int j = 0; j < 8; j++)
            #pragma unroll
            for (int k = 0; k < 4; k++) acc[j][k] = 0.f;

        #pragma unroll
        for (int t = 0; t < 16; t++) {
            uint32_t a0 = Qf[4*t], a1 = Qf[4*t+1], a2 = Qf[4*t+2], a3 = Qf[4*t+3];
            #pragma unroll
            for (int j = 0; j < 8; j++) {
                uint32_t b0 = __float_as_uint(Ks[(8*j + r4)*KPAD + 8*t + c4]);
                uint32_t b1 = __float_as_uint(Ks[(8*j + r4)*KPAD + 8*t + c4 + 4]);
                mma8(acc[j][0], acc[j][1], acc[j][2], acc[j][3], a0, a1, a2, a3, b0, b1);
            }
        }

        // ---- scale + edge mask + online softmax ----
        float tmax_lo = -1e30f, tmax_hi = -1e30f;
        #pragma unroll
        for (int j = 0; j < 8; j++) {
            int colb = n0 + 8*j + 2*c4;
            int e00, e01, e10, e11;
            if (is64) {
                int4 elo = *(const int4*)(edge + 2*((size_t)mlo * NS + colb));
                int4 ehi = *(const int4*)(edge + 2*((size_t)mhi * NS + colb));
                e00 = elo.x; e01 = elo.z; e10 = ehi.x; e11 = ehi.z;
            } else {
                int2 elo = *(const int2*)(edge + (size_t)mlo * NS + colb);
                int2 ehi = *(const int2*)(edge + (size_t)mhi * NS + colb);
                e00 = elo.x; e01 = elo.y; e10 = ehi.x; e11 = ehi.y;
            }
            acc[j][0] = acc[j][0] * scale + ((e00 == hid) ? 0.f : NEGV);
            acc[j][1] = acc[j][1] * scale + ((e01 == hid) ? 0.f : NEGV);
            acc[j][2] = acc[j][2] * scale + ((e10 == hid) ? 0.f : NEGV);
            acc[j][3] = acc[j][3] * scale + ((e11 == hid) ? 0.f : NEGV);
            tmax_lo = fmaxf(tmax_lo, fmaxf(acc[j][0], acc[j][1]));
            tmax_hi = fmaxf(tmax_hi, fmaxf(acc[j][2], acc[j][3]));
        }
        tmax_lo = fmaxf(tmax_lo, __shfl_xor_sync(0xffffffffu, tmax_lo, 1));
        tmax_lo = fmaxf(tmax_lo, __shfl_xor_sync(0xffffffffu, tmax_lo, 2));
        tmax_hi = fmaxf(tmax_hi, __shfl_xor_sync(0xffffffffu, tmax_hi, 1));
        tmax_hi = fmaxf(tmax_hi, __shfl_xor_sync(0xffffffffu, tmax_hi, 2));

        float nm_lo = fmaxf(rowmax_lo, tmax_lo);
        float nm_hi = fmaxf(rowmax_hi, tmax_hi);
        float f_lo = __expf(rowmax_lo - nm_lo);
        float f_hi = __expf(rowmax_hi - nm_hi);
        rowmax_lo = nm_lo; rowmax_hi = nm_hi;

        float tsum_lo = 0.f, tsum_hi = 0.f;
        #pragma unroll
        for (int j = 0; j < 8; j++) {
            float p0 = __expf(acc[j][0] - nm_lo);
            float p1 = __expf(acc[j][1] - nm_lo);
            float p2 = __expf(acc[j][2] - nm_hi);
            float p3 = __expf(acc[j][3] - nm_hi);
            tsum_lo += p0 + p1;
            tsum_hi += p2 + p3;
            // store P (tf32 bit pattern) for the PV A-fragments
            uint32_t u0 = f2tf(p0), u1 = f2tf(p1), u2 = f2tf(p2), u3 = f2tf(p3);
            *(uint2*)&Psw[(r4    )*PPAD + 8*j + 2*c4] = make_uint2(u0, u1);
            *(uint2*)&Psw[(r4 + 8)*PPAD + 8*j + 2*c4] = make_uint2(u2, u3);
        }
        tsum_lo += __shfl_xor_sync(0xffffffffu, tsum_lo, 1);
        tsum_lo += __shfl_xor_sync(0xffffffffu, tsum_lo, 2);
        tsum_hi += __shfl_xor_sync(0xffffffffu, tsum_hi, 1);
        tsum_hi += __shfl_xor_sync(0xffffffffu, tsum_hi, 2);

        rowsum_lo = rowsum_lo * f_lo + tsum_lo;
        rowsum_hi = rowsum_hi * f_hi + tsum_hi;
        if (f_lo < 1.f || f_hi < 1.f) {
            #pragma unroll
            for (int j = 0; j < 16; j++) {
                o[j][0] *= f_lo; o[j][1] *= f_lo;
                o[j][2] *= f_hi; o[j][3] *= f_hi;
            }
        }
        __syncwarp();

        // ---- O += P @ V ----
        #pragma unroll
        for (int t = 0; t < 8; t++) {
            uint32_t a0 = __float_as_uint(Psw[(r4    )*PPAD + 8*t + c4    ]);
            uint32_t a1 = __float_as_uint(Psw[(r4 + 8)*PPAD + 8*t + c4    ]);
            uint32_t a2 = __float_as_uint(Psw[(r4    )*PPAD + 8*t + c4 + 4]);
            uint32_t a3 = __float_as_uint(Psw[(r4 + 8)*PPAD + 8*t + c4 + 4]);
            #pragma unroll
            for (int j = 0; j < 16; j++) {
                uint32_t b0 = __float_as_uint(Vs[(8*t + c4    )*VPAD + 8*j + r4]);
                uint32_t b1 = __float_as_uint(Vs[(8*t + c4 + 4)*VPAD + 8*j + r4]);
                mma8(o[j][0], o[j][1], o[j][2], o[j][3], a0, a1, a2, a3, b0, b1);
            }
        }
        __syncthreads();
    }

    // Epilogue
    float inv_lo = 1.f / rowsum_lo;
    float inv_hi = 1.f / rowsum_hi;
    #pragma unroll
    for (int j = 0; j < 16; j++) {
        int d = 8*j + 2*c4;
        size_t blo = ((size_t)bh * NS + mlo) * ND + d;
        size_t bhi = ((size_t)bh * NS + mhi) * ND + d;
        *(float2*)&g_ctx[blo] = make_float2(o[j][0] * inv_lo, o[j][1] * inv_lo);
        *(float2*)&g_ctx[bhi] = make_float2(o[j][2] * inv_hi, o[j][3] * inv_hi);
    }
}

// ---------------------------------------------------------------------------
// K4: out projection (unchanged from R1)
// ---------------------------------------------------------------------------
__global__ __launch_bounds__(256) void outproj_kernel(const float* __restrict__ W_out,
                                                      const float* __restrict__ b_out,
                                                      float* __restrict__ out) {
    const int n0 = blockIdx.x * 64;
    const int m0 = blockIdx.y * 64;
    const int h = n0 >> 7;
    __shared__ float As[64][68];
    __shared__ float Bs[64][68];
    const int tid = threadIdx.x;
    const int tx = tid & 15, ty = tid >> 4;
    const int b = m0 >> 10;
    const int s0 = m0 & (NS - 1);
    const float* Ag = g_ctx + ((size_t)(b*NH + h) * NS + s0) * ND;

    float acc[4][4];
    #pragma unroll
    for (int i = 0; i < 4; i++)
        #pragma unroll
        for (int j = 0; j < 4; j++) acc[i][j] = 0.f;

    for (int kk = 0; kk < ND; kk += 64) {
        const int c = (tid & 15) * 4;
        for (int r = tid >> 4; r < 64; r += 16) {
            float4 a = *(const float4*)&Ag[(size_t)r * ND + kk + c];
            As[c+0][r] = a.x; As[c+1][r] = a.y; As[c+2][r] = a.z; As[c+3][r] = a.w;
            float4 w = *(const float4*)&W_out[(size_t)(n0 + r) * ND + kk + c];
            Bs[c+0][r] = w.x; Bs[c+1][r] = w.y; Bs[c+2][r] = w.z; Bs[c+3][r] = w.w;
        }
        __syncthreads();
        #pragma unroll 8
        for (int k = 0; k < 64; k++) {
            float4 a4 = *(const float4*)&As[k][ty*4];
            float4 b4 = *(const float4*)&Bs[k][tx*4];
            float av[4] = {a4.x, a4.y, a4.z, a4.w};
            float bv[4] = {b4.x, b4.y, b4.z, b4.w};
            #pragma unroll
            for (int i = 0; i < 4; i++)
                #pragma unroll
                for (int j = 0; j < 4; j++) acc[i][j] += av[i] * bv[j];
        }
        __syncthreads();
    }

    #pragma unroll
    for (int i = 0; i < 4; i++) {
        int row = m0 + ty*4 + i;
        int colb = n0 + tx*4;
        float4 r4 = make_float4(acc[i][0] + b_out[colb+0],
                                acc[i][1] + b_out[colb+1],
                                acc[i][2] + b_out[colb+2],
                                acc[i][3] + b_out[colb+3]);
        *(float4*)&out[(size_t)row * (NH*ND) + colb] = r4;
    }
}

// ---------------------------------------------------------------------------
extern "C" void kernel_launch(void* const* d_in, const int* in_sizes, int n_in,
                              void* d_out, int out_size) {
    const float* x     = (const float*)d_in[0];
    const int*   edge  = (const int*)d_in[1];
    const float* W_in  = (const float*)d_in[2];
    const float* b_in  = (const float*)d_in[3];
    const float* W_out = (const float*)d_in[4];
    const float* b_out = (const float*)d_in[5];
    float* out = (float*)d_out;

    static const size_t attn_smem = ATTN_SMEM_FLOATS * sizeof(float); // 172032
    cudaFuncSetAttribute((const void*)attn_kernel,
                         cudaFuncAttributeMaxDynamicSharedMemorySize,
                         (int)attn_smem);

    ln_stats_kernel<<<NB, 256>>>(x, edge);
    qkv_kernel<<<dim3(24, 256), 256>>>(x, W_in, b_in);
    attn_kernel<<<NB * NH * (NS / 128), 256, attn_smem>>>(edge);
    outproj_kernel<<<dim3(8, 256), 256>>>(W_out, b_out, out);
}

// round 3
// speedup vs baseline: 3.4029x; 1.4665x over previous
#include <cuda_runtime.h>
#include <math.h>
#include <stdint.h>

#define NB 16
#define NS 1024
#define ND 128
#define NH 4
#define NEGV -1e9f
#define LNEPS 1e-5f

// Scratch (device globals: allocation-free per harness rules)
__device__ float g_q[NB*NH*NS*ND];
__device__ float g_k[NB*NH*NS*ND];
__device__ float g_v[NB*NH*NS*ND];
__device__ float g_ctx[NB*NH*NS*ND];
__device__ float g_mean[NB];
__device__ float g_rstd[NB];
__device__ int   g_edge64;   // 1 if edge matrix is int64, 0 if int32

__device__ __forceinline__ uint32_t f2tf(float f) {
    uint32_t r;
    asm("cvt.rna.tf32.f32 %0, %1;" : "=r"(r) : "f"(f));
    return r;
}

__device__ __forceinline__ void mma8(float& d0, float& d1, float& d2, float& d3,
                                     uint32_t a0, uint32_t a1, uint32_t a2, uint32_t a3,
                                     uint32_t b0, uint32_t b1) {
    asm volatile("mma.sync.aligned.m16n8k8.row.col.f32.tf32.tf32.f32 "
                 "{%0,%1,%2,%3}, {%4,%5,%6,%7}, {%8,%9}, {%0,%1,%2,%3};"
                 : "+f"(d0), "+f"(d1), "+f"(d2), "+f"(d3)
                 : "r"(a0), "r"(a1), "r"(a2), "r"(a3), "r"(b0), "r"(b1));
}

__device__ __forceinline__ void cp16(float* dst_smem, const float* src_gmem) {
    uint32_t d = (uint32_t)__cvta_generic_to_shared(dst_smem);
    asm volatile("cp.async.cg.shared.global [%0], [%1], 16;" :: "r"(d), "l"(src_gmem));
}

// ---------------------------------------------------------------------------
// K1: per-batch LayerNorm stats over (S,D); also sniff edge dtype
// ---------------------------------------------------------------------------
__global__ void ln_stats_kernel(const float* __restrict__ x,
                                const int* __restrict__ edge) {
    int b = blockIdx.x;
    const float4* xb = (const float4*)(x + (size_t)b * NS * ND);
    const int n4 = NS * ND / 4;
    float s = 0.f, ss = 0.f;
    for (int i = threadIdx.x; i < n4; i += blockDim.x) {
        float4 v = xb[i];
        s  += v.x + v.y + v.z + v.w;
        ss += v.x*v.x + v.y*v.y + v.z*v.z + v.w*v.w;
    }
    __shared__ float sh[256], sh2[256];
    sh[threadIdx.x] = s; sh2[threadIdx.x] = ss;
    __syncthreads();
    for (int o = 128; o > 0; o >>= 1) {
        if (threadIdx.x < o) {
            sh[threadIdx.x]  += sh[threadIdx.x + o];
            sh2[threadIdx.x] += sh2[threadIdx.x + o];
        }
        __syncthreads();
    }
    if (threadIdx.x == 0) {
        float inv_n = 1.f / (float)(NS * ND);
        float mu  = sh[0] * inv_n;
        float var = sh2[0] * inv_n - mu * mu;
        g_mean[b] = mu;
        g_rstd[b] = rsqrtf(var + LNEPS);
        if (b == 0) {
            int any = 0;
            #pragma unroll
            for (int i = 0; i < 64; i++) any |= edge[2*i + 1];
            g_edge64 = (any == 0) ? 1 : 0;
        }
    }
}

// ---------------------------------------------------------------------------
// Shared GEMM geometry for projection kernels:
// block tile 128(M) x 64(N) x 128(K), 8 warps, warp = 16 rows x 64 cols.
// As[128][132] row-major [m][k]; Bs[64][132] [n][k] (weights are [n][k] already)
// ---------------------------------------------------------------------------
#define GPAD 132
#define GEMM_SMEM_FLOATS (128*GPAD + 64*GPAD)    // 101376 bytes

// K2: fused normalize + QKV projection (tf32 mma)
__global__ __launch_bounds__(256, 2) void qkv_kernel(const float* __restrict__ x,
                                                     const float* __restrict__ W_in,
                                                     const float* __restrict__ b_in) {
    extern __shared__ float sg[];
    float* As = sg;
    float* Bs = sg + 128*GPAD;

    const int tid  = threadIdx.x;
    const int w    = tid >> 5;
    const int lane = tid & 31;
    const int r4   = lane >> 2;
    const int c4   = lane & 3;

    const int n0 = blockIdx.x * 64;      // 24 tiles over 1536 cols
    const int m0 = blockIdx.y * 128;     // 128 tiles over 16384 rows
    const int b  = m0 >> 10;
    const float mean = g_mean[b], rstd = g_rstd[b];

    // Load A (normalized x) and B (weights) into smem
    {
        const int row16 = tid >> 4, c16 = (tid & 15) * 8;
        #pragma unroll
        for (int i = 0; i < 8; i++) {
            int row = row16 + i * 16;
            float4 a0 = *(const float4*)&x[(size_t)(m0 + row) * ND + c16];
            float4 a1 = *(const float4*)&x[(size_t)(m0 + row) * ND + c16 + 4];
            a0.x = (a0.x - mean) * rstd; a0.y = (a0.y - mean) * rstd;
            a0.z = (a0.z - mean) * rstd; a0.w = (a0.w - mean) * rstd;
            a1.x = (a1.x - mean) * rstd; a1.y = (a1.y - mean) * rstd;
            a1.z = (a1.z - mean) * rstd; a1.w = (a1.w - mean) * rstd;
            *(float4*)&As[row*GPAD + c16]     = a0;
            *(float4*)&As[row*GPAD + c16 + 4] = a1;
        }
        const int row8 = tid >> 5, c32 = (tid & 31) * 4;
        #pragma unroll
        for (int i = 0; i < 8; i++) {
            int row = row8 + i * 8;
            *(float4*)&Bs[row*GPAD + c32] =
                *(const float4*)&W_in[(size_t)(n0 + row) * ND + c32];
        }
    }
    __syncthreads();

    // Gather A fragments (tf32-rounded)
    uint32_t Af[64];
    {
        const int rl = 16*w + r4;
        #pragma unroll
        for (int t = 0; t < 16; t++) {
            Af[4*t+0] = f2tf(As[(rl    )*GPAD + 8*t + c4    ]);
            Af[4*t+1] = f2tf(As[(rl + 8)*GPAD + 8*t + c4    ]);
            Af[4*t+2] = f2tf(As[(rl    )*GPAD + 8*t + c4 + 4]);
            Af[4*t+3] = f2tf(As[(rl + 8)*GPAD + 8*t + c4 + 4]);
        }
    }

    float acc[8][4];
    #pragma unroll
    for (int j = 0; j < 8; j++)
        #pragma unroll
        for (int k = 0; k < 4; k++) acc[j][k] = 0.f;

    #pragma unroll
    for (int t = 0; t < 16; t++) {
        uint32_t a0 = Af[4*t], a1 = Af[4*t+1], a2 = Af[4*t+2], a3 = Af[4*t+3];
        #pragma unroll
        for (int j = 0; j < 8; j++) {
            uint32_t b0 = __float_as_uint(Bs[(8*j + r4)*GPAD + 8*t + c4]);
            uint32_t b1 = __float_as_uint(Bs[(8*j + r4)*GPAD + 8*t + c4 + 4]);
            mma8(acc[j][0], acc[j][1], acc[j][2], acc[j][3], a0, a1, a2, a3, b0, b1);
        }
    }

    // Epilogue: bias + scatter into q/k/v [B,H,S,D]
    const int rlo = m0 + 16*w + r4;
    const int rhi = rlo + 8;
    const int slo = rlo & (NS - 1);
    const int shi = rhi & (NS - 1);
    #pragma unroll
    for (int j = 0; j < 8; j++) {
        int colg = n0 + 8*j + 2*c4;
        float2 bias = *(const float2*)&b_in[colg];
        int hh = colg / 384;
        int r  = colg - hh * 384;
        int which = r >> 7;
        int d = r & 127;
        float* dst = (which == 0) ? g_q : (which == 1) ? g_k : g_v;
        size_t base = ((size_t)(b*NH + hh)) * NS * ND + d;
        *(float2*)&dst[base + (size_t)slo * ND] =
            make_float2(acc[j][0] + bias.x, acc[j][1] + bias.y);
        *(float2*)&dst[base + (size_t)shi * ND] =
            make_float2(acc[j][2] + bias.x, acc[j][3] + bias.y);
    }
}

// K4: out projection (tf32 mma)
__global__ __launch_bounds__(256, 2) void outproj_kernel(const float* __restrict__ W_out,
                                                         const float* __restrict__ b_out,
                                                         float* __restrict__ out) {
    extern __shared__ float sg[];
    float* As = sg;
    float* Bs = sg + 128*GPAD;

    const int tid  = threadIdx.x;
    const int w    = tid >> 5;
    const int lane = tid & 31;
    const int r4   = lane >> 2;
    const int c4   = lane & 3;

    const int n0 = blockIdx.x * 64;      // 8 tiles over 512 cols
    const int m0 = blockIdx.y * 128;     // 128 tiles over 16384 rows
    const int b  = m0 >> 10;
    const int s0 = m0 & (NS - 1);
    const int hh = n0 >> 7;
    const float* Ag = g_ctx + ((size_t)(b*NH + hh) * NS + s0) * ND;

    {
        const int row16 = tid >> 4, c16 = (tid & 15) * 8;
        #pragma unroll
        for (int i = 0; i < 8; i++) {
            int row = row16 + i * 16;
            *(float4*)&As[row*GPAD + c16]     = *(const float4*)&Ag[(size_t)row * ND + c16];
            *(float4*)&As[row*GPAD + c16 + 4] = *(const float4*)&Ag[(size_t)row * ND + c16 + 4];
        }
        const int row8 = tid >> 5, c32 = (tid & 31) * 4;
        #pragma unroll
        for (int i = 0; i < 8; i++) {
            int row = row8 + i * 8;
            *(float4*)&Bs[row*GPAD + c32] =
                *(const float4*)&W_out[(size_t)(n0 + row) * ND + c32];
        }
    }
    __syncthreads();

    uint32_t Af[64];
    {
        const int rl = 16*w + r4;
        #pragma unroll
        for (int t = 0; t < 16; t++) {
            Af[4*t+0] = f2tf(As[(rl    )*GPAD + 8*t + c4    ]);
            Af[4*t+1] = f2tf(As[(rl + 8)*GPAD + 8*t + c4    ]);
            Af[4*t+2] = f2tf(As[(rl    )*GPAD + 8*t + c4 + 4]);
            Af[4*t+3] = f2tf(As[(rl + 8)*GPAD + 8*t + c4 + 4]);
        }
    }

    float acc[8][4];
    #pragma unroll
    for (int j = 0; j < 8; j++)
        #pragma unroll
        for (int k = 0; k < 4; k++) acc[j][k] = 0.f;

    #pragma unroll
    for (int t = 0; t < 16; t++) {
        uint32_t a0 = Af[4*t], a1 = Af[4*t+1], a2 = Af[4*t+2], a3 = Af[4*t+3];
        #pragma unroll
        for (int j = 0; j < 8; j++) {
            uint32_t b0 = __float_as_uint(Bs[(8*j + r4)*GPAD + 8*t + c4]);
            uint32_t b1 = __float_as_uint(Bs[(8*j + r4)*GPAD + 8*t + c4 + 4]);
            mma8(acc[j][0], acc[j][1], acc[j][2], acc[j][3], a0, a1, a2, a3, b0, b1);
        }
    }

    const int rlo = m0 + 16*w + r4;
    const int rhi = rlo + 8;
    #pragma unroll
    for (int j = 0; j < 8; j++) {
        int colg = n0 + 8*j + 2*c4;
        float2 bias = *(const float2*)&b_out[colg];
        *(float2*)&out[(size_t)rlo * (NH*ND) + colg] =
            make_float2(acc[j][0] + bias.x, acc[j][1] + bias.y);
        *(float2*)&out[(size_t)rhi * (NH*ND) + colg] =
            make_float2(acc[j][2] + bias.x, acc[j][3] + bias.y);
    }
}

// ---------------------------------------------------------------------------
// K3: flash attention with tf32 mma.sync (m16n8k8), cp.async double-buffered
// (unchanged from R2)
// ---------------------------------------------------------------------------
#define KPAD 132
#define VPAD 136
#define PPAD 68
#define OFF_K0 0
#define OFF_K1 (64*KPAD)
#define OFF_V0 (2*64*KPAD)
#define OFF_V1 (2*64*KPAD + 64*VPAD)
#define OFF_P  (2*64*KPAD + 2*64*VPAD)
#define OFF_QSTG OFF_V1
#define ATTN_SMEM_FLOATS (2*64*KPAD + 2*64*VPAD + 128*PPAD)

__device__ __forceinline__ void load_kv_async(const float* __restrict__ Kg,
                                              const float* __restrict__ Vg,
                                              int n0, float* Ks, float* Vs, int tid) {
    #pragma unroll
    for (int i = 0; i < 8; i++) {
        int q = i * 256 + tid;
        int row = q >> 5, c4 = q & 31;
        cp16(&Ks[row*KPAD + c4*4], Kg + (size_t)(n0 + row) * ND + c4*4);
        cp16(&Vs[row*VPAD + c4*4], Vg + (size_t)(n0 + row) * ND + c4*4);
    }
}

__global__ __launch_bounds__(256, 1) void attn_kernel(const int* __restrict__ edge) {
    extern __shared__ float sm[];
    const int tid  = threadIdx.x;
    const int w    = tid >> 5;
    const int lane = tid & 31;
    const int r4   = lane >> 2;
    const int c4   = lane & 3;

    const int bh = blockIdx.x >> 3;
    const int qt = blockIdx.x & 7;
    const int h  = bh & 3;
    const int m0 = qt * 128;
    const int hid = h + 1;
    const float scale = 0.08838834764831845f;

    const float* Qg = g_q + (size_t)bh * NS * ND;
    const float* Kg = g_k + (size_t)bh * NS * ND;
    const float* Vg = g_v + (size_t)bh * NS * ND;
    const int is64 = g_edge64;

    load_kv_async(Kg, Vg, 0, sm + OFF_K0, sm + OFF_V0, tid);
    asm volatile("cp.async.commit_group;");

    {
        float* Qstg = sm + OFF_QSTG;
        #pragma unroll
        for (int i = 0; i < 16; i++) {
            int q = i * 256 + tid;
            int row = q >> 5, cc = q & 31;
            *(float4*)&Qstg[row*KPAD + cc*4] =
                *(const float4*)&Qg[(size_t)(m0 + row) * ND + cc*4];
        }
    }
    __syncthreads();

    uint32_t Qf[64];
    {
        const float* Qstg = sm + OFF_QSTG;
        const int rl = 16*w + r4;
        #pragma unroll
        for (int t = 0; t < 16; t++) {
            Qf[4*t+0] = f2tf(Qstg[(rl    )*KPAD + 8*t + c4    ]);
            Qf[4*t+1] = f2tf(Qstg[(rl + 8)*KPAD + 8*t + c4    ]);
            Qf[4*t+2] = f2tf(Qstg[(rl    )*KPAD + 8*t + c4 + 4]);
            Qf[4*t+3] = f2tf(Qstg[(rl + 8)*KPAD + 8*t + c4 + 4]);
        }
    }
    __syncthreads();

    float o[16][4];
    #pragma unroll
    for (int j = 0; j < 16; j++)
        #pragma unroll
        for (int k = 0; k < 4; k++) o[j][k] = 0.f;
    float rowmax_lo = -1e30f, rowmax_hi = -1e30f;
    float rowsum_lo = 0.f, rowsum_hi = 0.f;

    float* Psw = sm + OFF_P + w * 16 * PPAD;
    const int mlo = m0 + 16*w + r4;
    const int mhi = mlo + 8;

    for (int it = 0; it < 16; ++it) {
        const int buf = it & 1;
        if (it + 1 < 16) {
            load_kv_async(Kg, Vg, (it + 1) * 64,
                          sm + (buf ? OFF_K0 : OFF_K1),
                          sm + (buf ? OFF_V0 : OFF_V1), tid);
            asm volatile("cp.async.commit_group;");
            asm volatile("cp.async.wait_group 1;");
        } else {
            asm volatile("cp.async.wait_group 0;");
        }
        __syncthreads();

        const float* Ks = sm + (buf ? OFF_K1 : OFF_K0);
        const float* Vs = sm + (buf ? OFF_V1 : OFF_V0);
        const int n0 = it * 64;

        float acc[8][4];
        #pragma unroll
        for (int j = 0; j < 8; j++)
            #pragma unroll
            for (int k = 0; k < 4; k++) acc[j][k] = 0.f;

        #pragma unroll
        for (int t = 0; t < 16; t++) {
            uint32_t a0 = Qf[4*t], a1 = Qf[4*t+1], a2 = Qf[4*t+2], a3 = Qf[4*t+3];
            #pragma unroll
            for (int j = 0; j < 8; j++) {
                uint32_t b0 = __float_as_uint(Ks[(8*j + r4)*KPAD + 8*t + c4]);
                uint32_t b1 = __float_as_uint(Ks[(8*j + r4)*KPAD + 8*t + c4 + 4]);
                mma8(acc[j][0], acc[j][1], acc[j][2], acc[j][3], a0, a1, a2, a3, b0, b1);
            }
        }

        float tmax_lo = -1e30f, tmax_hi = -1e30f;
        #pragma unroll
        for (int j = 0; j < 8; j++) {
            int colb = n0 + 8*j + 2*c4;
            int e00, e01, e10, e11;
            if (is64) {
                int4 elo = *(const int4*)(edge + 2*((size_t)mlo * NS + colb));
                int4 ehi = *(const int4*)(edge + 2*((size_t)mhi * NS + colb));
                e00 = elo.x; e01 = elo.z; e10 = ehi.x; e11 = ehi.z;
            } else {
                int2 elo = *(const int2*)(edge + (size_t)mlo * NS + colb);
                int2 ehi = *(const int2*)(edge + (size_t)mhi * NS + colb);
                e00 = elo.x; e01 = elo.y; e10 = ehi.x; e11 = ehi.y;
            }
            acc[j][0] = acc[j][0] * scale + ((e00 == hid) ? 0.f : NEGV);
            acc[j][1] = acc[j][1] * scale + ((e01 == hid) ? 0.f : NEGV);
            acc[j][2] = acc[j][2] * scale + ((e10 == hid) ? 0.f : NEGV);
            acc[j][3] = acc[j][3] * scale + ((e11 == hid) ? 0.f : NEGV);
            tmax_lo = fmaxf(tmax_lo, fmaxf(acc[j][0], acc[j][1]));
            tmax_hi = fmaxf(tmax_hi, fmaxf(acc[j][2], acc[j][3]));
        }
        tmax_lo = fmaxf(tmax_lo, __shfl_xor_sync(0xffffffffu, tmax_lo, 1));
        tmax_lo = fmaxf(tmax_lo, __shfl_xor_sync(0xffffffffu, tmax_lo, 2));
        tmax_hi = fmaxf(tmax_hi, __shfl_xor_sync(0xffffffffu, tmax_hi, 1));
        tmax_hi = fmaxf(tmax_hi, __shfl_xor_sync(0xffffffffu, tmax_hi, 2));

        float nm_lo = fmaxf(rowmax_lo, tmax_lo);
        float nm_hi = fmaxf(rowmax_hi, tmax_hi);
        float f_lo = __expf(rowmax_lo - nm_lo);
        float f_hi = __expf(rowmax_hi - nm_hi);
        rowmax_lo = nm_lo; rowmax_hi = nm_hi;

        float tsum_lo = 0.f, tsum_hi = 0.f;
        #pragma unroll
        for (int j = 0; j < 8; j++) {
            float p0 = __expf(acc[j][0] - nm_lo);
            float p1 = __expf(acc[j][1] - nm_lo);
            float p2 = __expf(acc[j][2] - nm_hi);
            float p3 = __expf(acc[j][3] - nm_hi);
            tsum_lo += p0 + p1;
            tsum_hi += p2 + p3;
            uint32_t u0 = f2tf(p0), u1 = f2tf(p1), u2 = f2tf(p2), u3 = f2tf(p3);
            *(uint2*)&Psw[(r4    )*PPAD + 8*j + 2*c4] = make_uint2(u0, u1);
            *(uint2*)&Psw[(r4 + 8)*PPAD + 8*j + 2*c4] = make_uint2(u2, u3);
        }
        tsum_lo += __shfl_xor_sync(0xffffffffu, tsum_lo, 1);
        tsum_lo += __shfl_xor_sync(0xffffffffu, tsum_lo, 2);
        tsum_hi += __shfl_xor_sync(0xffffffffu, tsum_hi, 1);
        tsum_hi += __shfl_xor_sync(0xffffffffu, tsum_hi, 2);

        rowsum_lo = rowsum_lo * f_lo + tsum_lo;
        rowsum_hi = rowsum_hi * f_hi + tsum_hi;
        if (f_lo < 1.f || f_hi < 1.f) {
            #pragma unroll
            for (int j = 0; j < 16; j++) {
                o[j][0] *= f_lo; o[j][1] *= f_lo;
                o[j][2] *= f_hi; o[j][3] *= f_hi;
            }
        }
        __syncwarp();

        #pragma unroll
        for (int t = 0; t < 8; t++) {
            uint32_t a0 = __float_as_uint(Psw[(r4    )*PPAD + 8*t + c4    ]);
            uint32_t a1 = __float_as_uint(Psw[(r4 + 8)*PPAD + 8*t + c4    ]);
            uint32_t a2 = __float_as_uint(Psw[(r4    )*PPAD + 8*t + c4 + 4]);
            uint32_t a3 = __float_as_uint(Psw[(r4 + 8)*PPAD + 8*t + c4 + 4]);
            #pragma unroll
            for (int j = 0; j < 16; j++) {
                uint32_t b0 = __float_as_uint(Vs[(8*t + c4    )*VPAD + 8*j + r4]);
                uint32_t b1 = __float_as_uint(Vs[(8*t + c4 + 4)*VPAD + 8*j + r4]);
                mma8(o[j][0], o[j][1], o[j][2], o[j][3], a0, a1, a2, a3, b0, b1);
            }
        }
        __syncthreads();
    }

    float inv_lo = 1.f / rowsum_lo;
    float inv_hi = 1.f / rowsum_hi;
    #pragma unroll
    for (int j = 0; j < 16; j++) {
        int d = 8*j + 2*c4;
        size_t blo = ((size_t)bh * NS + mlo) * ND + d;
        size_t bhi = ((size_t)bh * NS + mhi) * ND + d;
        *(float2*)&g_ctx[blo] = make_float2(o[j][0] * inv_lo, o[j][1] * inv_lo);
        *(float2*)&g_ctx[bhi] = make_float2(o[j][2] * inv_hi, o[j][3] * inv_hi);
    }
}

// ---------------------------------------------------------------------------
extern "C" void kernel_launch(void* const* d_in, const int* in_sizes, int n_in,
                              void* d_out, int out_size) {
    const float* x     = (const float*)d_in[0];
    const int*   edge  = (const int*)d_in[1];
    const float* W_in  = (const float*)d_in[2];
    const float* b_in  = (const float*)d_in[3];
    const float* W_out = (const float*)d_in[4];
    const float* b_out = (const float*)d_in[5];
    float* out = (float*)d_out;

    static const size_t attn_smem = ATTN_SMEM_FLOATS * sizeof(float);
    static const size_t gemm_smem = GEMM_SMEM_FLOATS * sizeof(float);
    cudaFuncSetAttribute((const void*)attn_kernel,
                         cudaFuncAttributeMaxDynamicSharedMemorySize, (int)attn_smem);
    cudaFuncSetAttribute((const void*)qkv_kernel,
                         cudaFuncAttributeMaxDynamicSharedMemorySize, (int)gemm_smem);
    cudaFuncSetAttribute((const void*)outproj_kernel,
                         cudaFuncAttributeMaxDynamicSharedMemorySize, (int)gemm_smem);

    ln_stats_kernel<<<NB, 256>>>(x, edge);
    qkv_kernel<<<dim3(24, 128), 256, gemm_smem>>>(x, W_in, b_in);
    attn_kernel<<<NB * NH * (NS / 128), 256, attn_smem>>>(edge);
    outproj_kernel<<<dim3(8, 128), 256, gemm_smem>>>(W_out, b_out, out);
}

// round 4
// speedup vs baseline: 3.6709x; 1.0788x over previous
#include <cuda_runtime.h>
#include <math.h>
#include <stdint.h>

#define NB 16
#define NS 1024
#define ND 128
#define NH 4
#define LNEPS 1e-5f

// Scratch (device globals: allocation-free per harness rules)
__device__ float g_q[NB*NH*NS*ND];
__device__ float g_k[NB*NH*NS*ND];
__device__ float g_v[NB*NH*NS*ND];
__device__ float g_ctx[NB*NH*NS*ND];
__device__ float g_mean[NB];
__device__ float g_rstd[NB];
__device__ float g_wsum[NH*3*ND];            // per-col sum of W_in rows
__device__ unsigned long long g_mbits[NH*NS*16];  // [h][s][keytile] bitmask
__device__ int   g_edge64;   // 1 if edge matrix is int64, 0 if int32

__device__ __forceinline__ uint32_t f2tf(float f) {
    uint32_t r;
    asm("cvt.rna.tf32.f32 %0, %1;" : "=r"(r) : "f"(f));
    return r;
}

__device__ __forceinline__ void mma8(float& d0, float& d1, float& d2, float& d3,
                                     uint32_t a0, uint32_t a1, uint32_t a2, uint32_t a3,
                                     uint32_t b0, uint32_t b1) {
    asm volatile("mma.sync.aligned.m16n8k8.row.col.f32.tf32.tf32.f32 "
                 "{%0,%1,%2,%3}, {%4,%5,%6,%7}, {%8,%9}, {%0,%1,%2,%3};"
                 : "+f"(d0), "+f"(d1), "+f"(d2), "+f"(d3)
                 : "r"(a0), "r"(a1), "r"(a2), "r"(a3), "r"(b0), "r"(b1));
}

__device__ __forceinline__ void cp16(float* dst_smem, const float* src_gmem) {
    uint32_t d = (uint32_t)__cvta_generic_to_shared(dst_smem);
    asm volatile("cp.async.cg.shared.global [%0], [%1], 16;" :: "r"(d), "l"(src_gmem));
}

// ---------------------------------------------------------------------------
// K1: per-batch LayerNorm stats over (S,D); also sniff edge dtype
// ---------------------------------------------------------------------------
__global__ void ln_stats_kernel(const float* __restrict__ x,
                                const int* __restrict__ edge) {
    int b = blockIdx.x;
    const float4* xb = (const float4*)(x + (size_t)b * NS * ND);
    const int n4 = NS * ND / 4;
    float s = 0.f, ss = 0.f;
    for (int i = threadIdx.x; i < n4; i += blockDim.x) {
        float4 v = xb[i];
        s  += v.x + v.y + v.z + v.w;
        ss += v.x*v.x + v.y*v.y + v.z*v.z + v.w*v.w;
    }
    __shared__ float sh[256], sh2[256];
    sh[threadIdx.x] = s; sh2[threadIdx.x] = ss;
    __syncthreads();
    for (int o = 128; o > 0; o >>= 1) {
        if (threadIdx.x < o) {
            sh[threadIdx.x]  += sh[threadIdx.x + o];
            sh2[threadIdx.x] += sh2[threadIdx.x + o];
        }
        __syncthreads();
    }
    if (threadIdx.x == 0) {
        float inv_n = 1.f / (float)(NS * ND);
        float mu  = sh[0] * inv_n;
        float var = sh2[0] * inv_n - mu * mu;
        g_mean[b] = mu;
        g_rstd[b] = rsqrtf(var + LNEPS);
        if (b == 0) {
            int any = 0;
            #pragma unroll
            for (int i = 0; i < 64; i++) any |= edge[2*i + 1];
            g_edge64 = (any == 0) ? 1 : 0;
        }
    }
}

// ---------------------------------------------------------------------------
// K1b: prep — build per-head edge bitmasks + W_in column sums
// ---------------------------------------------------------------------------
__global__ void prep_kernel(const int* __restrict__ edge,
                            const float* __restrict__ W_in) {
    int blk = blockIdx.x;
    if (blk < 64) {
        int idx = blk * 256 + threadIdx.x;     // 0..16383
        int s = idx >> 4, t64 = idx & 15;
        unsigned long long m0 = 0, m1 = 0, m2 = 0, m3 = 0;
        if (g_edge64) {
            const int4* p = (const int4*)(edge + 2*((size_t)s*NS + t64*64));
            #pragma unroll
            for (int i = 0; i < 32; i++) {
                int4 v = p[i];
                unsigned long long b0 = 1ull << (2*i), b1 = 1ull << (2*i+1);
                if (v.x == 1) m0 |= b0;  if (v.z == 1) m0 |= b1;
                if (v.x == 2) m1 |= b0;  if (v.z == 2) m1 |= b1;
                if (v.x == 3) m2 |= b0;  if (v.z == 3) m2 |= b1;
                if (v.x == 4) m3 |= b0;  if (v.z == 4) m3 |= b1;
            }
        } else {
            const int4* p = (const int4*)(edge + ((size_t)s*NS + t64*64));
            #pragma unroll
            for (int i = 0; i < 16; i++) {
                int4 v = p[i];
                int e[4] = {v.x, v.y, v.z, v.w};
                #pragma unroll
                for (int q = 0; q < 4; q++) {
                    unsigned long long b = 1ull << (4*i + q);
                    if (e[q] == 1) m0 |= b;
                    if (e[q] == 2) m1 |= b;
                    if (e[q] == 3) m2 |= b;
                    if (e[q] == 4) m3 |= b;
                }
            }
        }
        g_mbits[(0*NS + s)*16 + t64] = m0;
        g_mbits[(1*NS + s)*16 + t64] = m1;
        g_mbits[(2*NS + s)*16 + t64] = m2;
        g_mbits[(3*NS + s)*16 + t64] = m3;
    } else {
        int col = (blk - 64) * 256 + threadIdx.x;   // 0..1535
        float s = 0.f;
        const float4* p = (const float4*)(W_in + (size_t)col * ND);
        #pragma unroll
        for (int i = 0; i < 32; i++) {
            float4 v = p[i];
            s += v.x + v.y + v.z + v.w;
        }
        g_wsum[col] = s;
    }
}

// ---------------------------------------------------------------------------
// Projection kernels: A-resident (registers) loop over B col-tiles.
// block = 128 rows x 256 threads; per warp 16 rows; NT col tiles of 64.
// smem: As[128][132] (staging, freed logically after frag gather),
//       Bs[2][64][132] double-buffered via cp.async.
// ---------------------------------------------------------------------------
#define PJ 132
#define PROJ_SMEM_FLOATS (128*PJ + 2*64*PJ)   // 135168 bytes

// K2: fused LN + QKV projection. LN folded into epilogue:
//   out = rstd*acc_raw + (b_in[c] - mean*rstd*wsum[c])
__global__ __launch_bounds__(256, 1) void qkv_kernel(const float* __restrict__ x,
                                                     const float* __restrict__ W_in,
                                                     const float* __restrict__ b_in) {
    extern __shared__ float sg[];
    float* As = sg;
    float* Bs0 = sg + 128*PJ;
    float* Bs1 = sg + 128*PJ + 64*PJ;

    const int tid  = threadIdx.x;
    const int w    = tid >> 5;
    const int lane = tid & 31;
    const int r4   = lane >> 2;
    const int c4   = lane & 3;

    const int colbase = blockIdx.x * 768;     // 2 halves of 1536
    const int m0 = blockIdx.y * 128;
    const int b  = blockIdx.y >> 3;
    const float mean = g_mean[b], rstd = g_rstd[b];
    const float mr = mean * rstd;

    // Issue A (raw x) + B tile 0
    #pragma unroll
    for (int i = 0; i < 16; i++) {
        int q = i * 256 + tid;
        int row = q >> 5, c = (q & 31) * 4;
        cp16(&As[row*PJ + c], &x[(size_t)(m0 + row) * ND + c]);
    }
    #pragma unroll
    for (int i = 0; i < 8; i++) {
        int q = i * 256 + tid;
        int row = q >> 5, c = (q & 31) * 4;
        cp16(&Bs0[row*PJ + c], &W_in[(size_t)(colbase + row) * ND + c]);
    }
    asm volatile("cp.async.commit_group;");
    asm volatile("cp.async.wait_group 0;");
    __syncthreads();

    // Gather A fragments (tf32-rounded raw x)
    uint32_t Af[64];
    {
        const int rl = 16*w + r4;
        #pragma unroll
        for (int t = 0; t < 16; t++) {
            Af[4*t+0] = f2tf(As[(rl    )*PJ + 8*t + c4    ]);
            Af[4*t+1] = f2tf(As[(rl + 8)*PJ + 8*t + c4    ]);
            Af[4*t+2] = f2tf(As[(rl    )*PJ + 8*t + c4 + 4]);
            Af[4*t+3] = f2tf(As[(rl + 8)*PJ + 8*t + c4 + 4]);
        }
    }

    const int rlo = m0 + 16*w + r4;
    const int rhi = rlo + 8;
    const int slo = rlo & (NS - 1);
    const int shi = rhi & (NS - 1);

    #define NTQ 12
    for (int nt = 0; nt < NTQ; nt++) {
        const int buf = nt & 1;
        float* Bcur = buf ? Bs1 : Bs0;
        float* Bnxt = buf ? Bs0 : Bs1;
        // B(nt) is ready (waited previous iter / preloop); all warps synced.
        if (nt + 1 < NTQ) {
            const int nrow = colbase + (nt + 1) * 64;
            #pragma unroll
            for (int i = 0; i < 8; i++) {
                int q = i * 256 + tid;
                int row = q >> 5, c = (q & 31) * 4;
                cp16(&Bnxt[row*PJ + c], &W_in[(size_t)(nrow + row) * ND + c]);
            }
            asm volatile("cp.async.commit_group;");
        }

        float acc[8][4];
        #pragma unroll
        for (int j = 0; j < 8; j++)
            #pragma unroll
            for (int k = 0; k < 4; k++) acc[j][k] = 0.f;

        #pragma unroll
        for (int t = 0; t < 16; t++) {
            uint32_t a0 = Af[4*t], a1 = Af[4*t+1], a2 = Af[4*t+2], a3 = Af[4*t+3];
            #pragma unroll
            for (int j = 0; j < 8; j++) {
                uint32_t b0 = __float_as_uint(Bcur[(8*j + r4)*PJ + 8*t + c4]);
                uint32_t b1 = __float_as_uint(Bcur[(8*j + r4)*PJ + 8*t + c4 + 4]);
                mma8(acc[j][0], acc[j][1], acc[j][2], acc[j][3], a0, a1, a2, a3, b0, b1);
            }
        }

        // Epilogue: LN-fold + bias + scatter
        const int n0 = colbase + nt * 64;
        #pragma unroll
        for (int j = 0; j < 8; j++) {
            int colg = n0 + 8*j + 2*c4;
            float2 bias = *(const float2*)&b_in[colg];
            float2 ws   = *(const float2*)&g_wsum[colg];
            float off0 = bias.x - mr * ws.x;
            float off1 = bias.y - mr * ws.y;
            int hh = colg / 384;
            int r  = colg - hh * 384;
            int which = r >> 7;
            int d = r & 127;
            float* dst = (which == 0) ? g_q : (which == 1) ? g_k : g_v;
            size_t base = ((size_t)(b*NH + hh)) * NS * ND + d;
            *(float2*)&dst[base + (size_t)slo * ND] =
                make_float2(rstd*acc[j][0] + off0, rstd*acc[j][1] + off1);
            *(float2*)&dst[base + (size_t)shi * ND] =
                make_float2(rstd*acc[j][2] + off0, rstd*acc[j][3] + off1);
        }

        if (nt + 1 < NTQ) {
            asm volatile("cp.async.wait_group 0;");
            __syncthreads();
        }
    }
}

// K4: out projection. grid (4 heads, 128 row tiles), NT=2 col tiles.
__global__ __launch_bounds__(256, 1) void outproj_kernel(const float* __restrict__ W_out,
                                                         const float* __restrict__ b_out,
                                                         float* __restrict__ out) {
    extern __shared__ float sg[];
    float* As = sg;
    float* Bs0 = sg + 128*PJ;
    float* Bs1 = sg + 128*PJ + 64*PJ;

    const int tid  = threadIdx.x;
    const int w    = tid >> 5;
    const int lane = tid & 31;
    const int r4   = lane >> 2;
    const int c4   = lane & 3;

    const int hh = blockIdx.x;               // head
    const int m0 = blockIdx.y * 128;
    const int b  = blockIdx.y >> 3;
    const int s0 = m0 & (NS - 1);
    const float* Ag = g_ctx + ((size_t)(b*NH + hh) * NS + s0) * ND;
    const int colbase = hh * 128;

    #pragma unroll
    for (int i = 0; i < 16; i++) {
        int q = i * 256 + tid;
        int row = q >> 5, c = (q & 31) * 4;
        cp16(&As[row*PJ + c], &Ag[(size_t)row * ND + c]);
    }
    #pragma unroll
    for (int i = 0; i < 8; i++) {
        int q = i * 256 + tid;
        int row = q >> 5, c = (q & 31) * 4;
        cp16(&Bs0[row*PJ + c], &W_out[(size_t)(colbase + row) * ND + c]);
    }
    asm volatile("cp.async.commit_group;");
    asm volatile("cp.async.wait_group 0;");
    __syncthreads();

    uint32_t Af[64];
    {
        const int rl = 16*w + r4;
        #pragma unroll
        for (int t = 0; t < 16; t++) {
            Af[4*t+0] = f2tf(As[(rl    )*PJ + 8*t + c4    ]);
            Af[4*t+1] = f2tf(As[(rl + 8)*PJ + 8*t + c4    ]);
            Af[4*t+2] = f2tf(As[(rl    )*PJ + 8*t + c4 + 4]);
            Af[4*t+3] = f2tf(As[(rl + 8)*PJ + 8*t + c4 + 4]);
        }
    }

    const int rlo = m0 + 16*w + r4;
    const int rhi = rlo + 8;

    #pragma unroll
    for (int nt = 0; nt < 2; nt++) {
        float* Bcur = nt ? Bs1 : Bs0;
        float* Bnxt = nt ? Bs0 : Bs1;
        if (nt == 0) {
            const int nrow = colbase + 64;
            #pragma unroll
            for (int i = 0; i < 8; i++) {
                int q = i * 256 + tid;
                int row = q >> 5, c = (q & 31) * 4;
                cp16(&Bnxt[row*PJ + c], &W_out[(size_t)(nrow + row) * ND + c]);
            }
            asm volatile("cp.async.commit_group;");
        }

        float acc[8][4];
        #pragma unroll
        for (int j = 0; j < 8; j++)
            #pragma unroll
            for (int k = 0; k < 4; k++) acc[j][k] = 0.f;

        #pragma unroll
        for (int t = 0; t < 16; t++) {
            uint32_t a0 = Af[4*t], a1 = Af[4*t+1], a2 = Af[4*t+2], a3 = Af[4*t+3];
            #pragma unroll
            for (int j = 0; j < 8; j++) {
                uint32_t b0 = __float_as_uint(Bcur[(8*j + r4)*PJ + 8*t + c4]);
                uint32_t b1 = __float_as_uint(Bcur[(8*j + r4)*PJ + 8*t + c4 + 4]);
                mma8(acc[j][0], acc[j][1], acc[j][2], acc[j][3], a0, a1, a2, a3, b0, b1);
            }
        }

        const int n0 = colbase + nt * 64;
        #pragma unroll
        for (int j = 0; j < 8; j++) {
            int colg = n0 + 8*j + 2*c4;
            float2 bias = *(const float2*)&b_out[colg];
            *(float2*)&out[(size_t)rlo * (NH*ND) + colg] =
                make_float2(acc[j][0] + bias.x, acc[j][1] + bias.y);
            *(float2*)&out[(size_t)rhi * (NH*ND) + colg] =
                make_float2(acc[j][2] + bias.x, acc[j][3] + bias.y);
        }

        if (nt == 0) {
            asm volatile("cp.async.wait_group 0;");
            __syncthreads();
        }
    }
}

// ---------------------------------------------------------------------------
// K3: flash attention, tf32 mma, bitmask edges, no-max softmax.
// Scores are provably tiny (|s|<~1 typical, <13 hard bound) -> exp safe
// without max subtraction; masked lanes get exact 0.
// ---------------------------------------------------------------------------
#define KPAD 132
#define VPAD 136
#define PPAD 68
#define OFF_K0 0
#define OFF_K1 (64*KPAD)
#define OFF_V0 (2*64*KPAD)
#define OFF_V1 (2*64*KPAD + 64*VPAD)
#define OFF_P  (2*64*KPAD + 2*64*VPAD)
#define OFF_QSTG OFF_V1
#define ATTN_SMEM_FLOATS (2*64*KPAD + 2*64*VPAD + 128*PPAD)

__device__ __forceinline__ void load_kv_async(const float* __restrict__ Kg,
                                              const float* __restrict__ Vg,
                                              int n0, float* Ks, float* Vs, int tid) {
    #pragma unroll
    for (int i = 0; i < 8; i++) {
        int q = i * 256 + tid;
        int row = q >> 5, c4 = q & 31;
        cp16(&Ks[row*KPAD + c4*4], Kg + (size_t)(n0 + row) * ND + c4*4);
        cp16(&Vs[row*VPAD + c4*4], Vg + (size_t)(n0 + row) * ND + c4*4);
    }
}

__global__ __launch_bounds__(256, 1) void attn_kernel() {
    extern __shared__ float sm[];
    const int tid  = threadIdx.x;
    const int w    = tid >> 5;
    const int lane = tid & 31;
    const int r4   = lane >> 2;
    const int c4   = lane & 3;

    const int bh = blockIdx.x >> 3;
    const int qt = blockIdx.x & 7;
    const int h  = bh & 3;
    const int m0 = qt * 128;
    const float scale = 0.08838834764831845f;

    const float* Qg = g_q + (size_t)bh * NS * ND;
    const float* Kg = g_k + (size_t)bh * NS * ND;
    const float* Vg = g_v + (size_t)bh * NS * ND;

    load_kv_async(Kg, Vg, 0, sm + OFF_K0, sm + OFF_V0, tid);
    asm volatile("cp.async.commit_group;");

    {
        float* Qstg = sm + OFF_QSTG;
        #pragma unroll
        for (int i = 0; i < 16; i++) {
            int q = i * 256 + tid;
            int row = q >> 5, cc = q & 31;
            *(float4*)&Qstg[row*KPAD + cc*4] =
                *(const float4*)&Qg[(size_t)(m0 + row) * ND + cc*4];
        }
    }
    __syncthreads();

    // Q fragments with softmax scale folded in
    uint32_t Qf[64];
    {
        const float* Qstg = sm + OFF_QSTG;
        const int rl = 16*w + r4;
        #pragma unroll
        for (int t = 0; t < 16; t++) {
            Qf[4*t+0] = f2tf(Qstg[(rl    )*KPAD + 8*t + c4    ] * scale);
            Qf[4*t+1] = f2tf(Qstg[(rl + 8)*KPAD + 8*t + c4    ] * scale);
            Qf[4*t+2] = f2tf(Qstg[(rl    )*KPAD + 8*t + c4 + 4] * scale);
            Qf[4*t+3] = f2tf(Qstg[(rl + 8)*KPAD + 8*t + c4 + 4] * scale);
        }
    }
    __syncthreads();

    float o[16][4];
    #pragma unroll
    for (int j = 0; j < 16; j++)
        #pragma unroll
        for (int k = 0; k < 4; k++) o[j][k] = 0.f;
    float rs_lo = 0.f, rs_hi = 0.f;

    float* Psw = sm + OFF_P + w * 16 * PPAD;
    const int mlo = m0 + 16*w + r4;
    const int mhi = mlo + 8;
    const unsigned long long* mb_lo_base = &g_mbits[((size_t)h*NS + mlo)*16];
    const unsigned long long* mb_hi_base = &g_mbits[((size_t)h*NS + mhi)*16];

    for (int it = 0; it < 16; ++it) {
        const int buf = it & 1;
        if (it + 1 < 16) {
            load_kv_async(Kg, Vg, (it + 1) * 64,
                          sm + (buf ? OFF_K0 : OFF_K1),
                          sm + (buf ? OFF_V0 : OFF_V1), tid);
            asm volatile("cp.async.commit_group;");
            asm volatile("cp.async.wait_group 1;");
        } else {
            asm volatile("cp.async.wait_group 0;");
        }
        __syncthreads();

        // Mask bits for this 64-key tile (2 x LDG.64, hidden under QK mma)
        const unsigned long long mb_lo = mb_lo_base[it];
        const unsigned long long mb_hi = mb_hi_base[it];

        const float* Ks = sm + (buf ? OFF_K1 : OFF_K0);
        const float* Vs = sm + (buf ? OFF_V1 : OFF_V0);

        // ---- QK^T (already scaled via Qf) ----
        float acc[8][4];
        #pragma unroll
        for (int j = 0; j < 8; j++)
            #pragma unroll
            for (int k = 0; k < 4; k++) acc[j][k] = 0.f;

        #pragma unroll
        for (int t = 0; t < 16; t++) {
            uint32_t a0 = Qf[4*t], a1 = Qf[4*t+1], a2 = Qf[4*t+2], a3 = Qf[4*t+3];
            #pragma unroll
            for (int j = 0; j < 8; j++) {
                uint32_t b0 = __float_as_uint(Ks[(8*j + r4)*KPAD + 8*t + c4]);
                uint32_t b1 = __float_as_uint(Ks[(8*j + r4)*KPAD + 8*t + c4 + 4]);
                mma8(acc[j][0], acc[j][1], acc[j][2], acc[j][3], a0, a1, a2, a3, b0, b1);
            }
        }

        // ---- exp + mask-select + P store ----
        #pragma unroll
        for (int j = 0; j < 8; j++) {
            unsigned blo = (unsigned)(mb_lo >> (8*j + 2*c4));
            unsigned bhi = (unsigned)(mb_hi >> (8*j + 2*c4));
            float p0 = (blo & 1u) ? __expf(acc[j][0]) : 0.f;
            float p1 = (blo & 2u) ? __expf(acc[j][1]) : 0.f;
            float p2 = (bhi & 1u) ? __expf(acc[j][2]) : 0.f;
            float p3 = (bhi & 2u) ? __expf(acc[j][3]) : 0.f;
            rs_lo += p0 + p1;
            rs_hi += p2 + p3;
            uint32_t u0 = f2tf(p0), u1 = f2tf(p1), u2 = f2tf(p2), u3 = f2tf(p3);
            *(uint2*)&Psw[(r4    )*PPAD + 8*j + 2*c4] = make_uint2(u0, u1);
            *(uint2*)&Psw[(r4 + 8)*PPAD + 8*j + 2*c4] = make_uint2(u2, u3);
        }
        __syncwarp();

        // ---- O += P @ V ----
        #pragma unroll
        for (int t = 0; t < 8; t++) {
            uint32_t a0 = __float_as_uint(Psw[(r4    )*PPAD + 8*t + c4    ]);
            uint32_t a1 = __float_as_uint(Psw[(r4 + 8)*PPAD + 8*t + c4    ]);
            uint32_t a2 = __float_as_uint(Psw[(r4    )*PPAD + 8*t + c4 + 4]);
            uint32_t a3 = __float_as_uint(Psw[(r4 + 8)*PPAD + 8*t + c4 + 4]);
            #pragma unroll
            for (int j = 0; j < 16; j++) {
                uint32_t b0 = __float_as_uint(Vs[(8*t + c4    )*VPAD + 8*j + r4]);
                uint32_t b1 = __float_as_uint(Vs[(8*t + c4 + 4)*VPAD + 8*j + r4]);
                mma8(o[j][0], o[j][1], o[j][2], o[j][3], a0, a1, a2, a3, b0, b1);
            }
        }
        __syncthreads();
    }

    // Epilogue: single rowsum reduction + normalize + store
    rs_lo += __shfl_xor_sync(0xffffffffu, rs_lo, 1);
    rs_lo += __shfl_xor_sync(0xffffffffu, rs_lo, 2);
    rs_hi += __shfl_xor_sync(0xffffffffu, rs_hi, 1);
    rs_hi += __shfl_xor_sync(0xffffffffu, rs_hi, 2);
    float inv_lo = 1.f / rs_lo;
    float inv_hi = 1.f / rs_hi;
    #pragma unroll
    for (int j = 0; j < 16; j++) {
        int d = 8*j + 2*c4;
        size_t blo = ((size_t)bh * NS + mlo) * ND + d;
        size_t bhi = ((size_t)bh * NS + mhi) * ND + d;
        *(float2*)&g_ctx[blo] = make_float2(o[j][0] * inv_lo, o[j][1] * inv_lo);
        *(float2*)&g_ctx[bhi] = make_float2(o[j][2] * inv_hi, o[j][3] * inv_hi);
    }
}

// ---------------------------------------------------------------------------
extern "C" void kernel_launch(void* const* d_in, const int* in_sizes, int n_in,
                              void* d_out, int out_size) {
    const float* x     = (const float*)d_in[0];
    const int*   edge  = (const int*)d_in[1];
    const float* W_in  = (const float*)d_in[2];
    const float* b_in  = (const float*)d_in[3];
    const float* W_out = (const float*)d_in[4];
    const float* b_out = (const float*)d_in[5];
    float* out = (float*)d_out;

    static const size_t attn_smem = ATTN_SMEM_FLOATS * sizeof(float);
    static const size_t proj_smem = PROJ_SMEM_FLOATS * sizeof(float);
    cudaFuncSetAttribute((const void*)attn_kernel,
                         cudaFuncAttributeMaxDynamicSharedMemorySize, (int)attn_smem);
    cudaFuncSetAttribute((const void*)qkv_kernel,
                         cudaFuncAttributeMaxDynamicSharedMemorySize, (int)proj_smem);
    cudaFuncSetAttribute((const void*)outproj_kernel,
                         cudaFuncAttributeMaxDynamicSharedMemorySize, (int)proj_smem);

    ln_stats_kernel<<<NB, 256>>>(x, edge);
    prep_kernel<<<70, 256>>>(edge, W_in);
    qkv_kernel<<<dim3(2, 128), 256, proj_smem>>>(x, W_in, b_in);
    attn_kernel<<<NB * NH * (NS / 128), 256, attn_smem>>>();
    outproj_kernel<<<dim3(4, 128), 256, proj_smem>>>(W_out, b_out, out);
}